// round 8
// baseline (speedup 1.0000x reference)
#include <cuda_runtime.h>
#include <cstdint>
#include <cstddef>

// Problem constants
#define BB   32
#define TT   4096
#define DD   512
#define GG   8
#define OUTD 512

#define NCHUNK 32
#define CHUNK  128          // tokens per (b,c) chunk
#define DHF    64           // float4 lanes per d-half (256 floats)

// K3 tiling: one-shot tiles, split-K over 16 d-tiles of 32
#define K3B   32            // o-tile width
#define K3D   32            // d-tile depth
#define K3_ND (DD / K3D)    // 16
#define MP3   36            // mean smem pitch (floats); 144 B = 16 B multiple

// -------- device scratch (no allocations allowed) --------
__device__ int   g_idx[TT];                               // token indices sorted by type
__device__ int   g_segstart[GG + 1];                      // group segment boundaries
__device__ float g_part[(size_t)BB * GG * NCHUNK * DD];   // partial sums [b][g][c][d] (16 MB)
__device__ float g_pcnt[BB * GG * NCHUNK];                // partial counts [b][g][c]
__device__ float g_means[(size_t)GG * BB * DD];           // means [g][b][d] (0.5 MB)
__device__ float g_ppart[(size_t)K3_ND * BB * GG * OUTD]; // gemm partials [dq][b][g][o] (8 MB)

// =====================================================================
// K1: deterministic stable counting sort of token_types (1 block, 512 thr)
// =====================================================================
__global__ void __launch_bounds__(512) k_sort(const int* __restrict__ types) {
    __shared__ int s[GG][512];
    __shared__ int base_s[GG + 1];
    const int tid = threadIdx.x;

    int ty[8];
    int lc[GG];
#pragma unroll
    for (int g = 0; g < GG; g++) lc[g] = 0;
#pragma unroll
    for (int k = 0; k < 8; k++) {
        const int t  = tid * 8 + k;
        const int tt = types[t];
        ty[k] = tt;
#pragma unroll
        for (int g = 0; g < GG; g++) lc[g] += (tt == g);
    }
#pragma unroll
    for (int g = 0; g < GG; g++) s[g][tid] = lc[g];
    __syncthreads();

    for (int off = 1; off < 512; off <<= 1) {
        int add[GG];
#pragma unroll
        for (int g = 0; g < GG; g++) add[g] = (tid >= off) ? s[g][tid - off] : 0;
        __syncthreads();
#pragma unroll
        for (int g = 0; g < GG; g++) s[g][tid] += add[g];
        __syncthreads();
    }

    if (tid == 0) {
        int b0 = 0;
        for (int g = 0; g < GG; g++) {
            base_s[g] = b0;
            g_segstart[g] = b0;
            b0 += s[g][511];
        }
        base_s[GG] = b0;
        g_segstart[GG] = b0;
    }
    __syncthreads();

    int cur[GG];
#pragma unroll
    for (int g = 0; g < GG; g++) cur[g] = base_s[g] + s[g][tid] - lc[g];
#pragma unroll
    for (int k = 0; k < 8; k++) {
        const int t  = tid * 8 + k;
        const int tt = ty[k];
#pragma unroll
        for (int g = 0; g < GG; g++) {
            if (tt == g) { g_idx[cur[g]] = t; cur[g]++; }
        }
    }
}

// =====================================================================
// K2: segmented partial sums, valid-token compaction, d-half split.
// Grid (B=32, NCHUNK=32, 2) = 2048 blocks, 128 thr.
// sub = tid>>6 processes every other valid token; halves combined in smem.
// =====================================================================
__global__ void __launch_bounds__(128, 10) k_partial(const float* __restrict__ batch,
                                                     const int* __restrict__ mask) {
    __shared__ __align__(16) float4 comb4[GG][DHF];  // sub1 accumulators (8 KB), 16B aligned
    __shared__ int   t_c[CHUNK];          // compacted valid token ids
    __shared__ int   scan_s[CHUNK + 1];   // exclusive scan of valid flags
    __shared__ int   seg_s[GG + 1];       // global segment bounds
    __shared__ int   segc_s[GG + 1];      // compacted local segment bounds
    __shared__ int   wsum_s[4];           // per-warp scan totals

    const int tid = threadIdx.x;
    const int b   = blockIdx.x;
    const int c   = blockIdx.y;
    const int dh  = blockIdx.z;
    const int c0  = c * CHUNK;

    if (tid < GG + 1) seg_s[tid] = g_segstart[tid];

    // ---- stage + block-wide compaction scan ----
    const int t = g_idx[c0 + tid];
    const int v = mask[b * TT + t] ? 0 : 1;   // int32 bool: nonzero = padded

    const int lane = tid & 31;
    const int w    = tid >> 5;
    int x = v;
#pragma unroll
    for (int off = 1; off < 32; off <<= 1) {
        const int y = __shfl_up_sync(0xffffffffu, x, off);
        if (lane >= off) x += y;
    }
    if (lane == 31) wsum_s[w] = x;
    __syncthreads();
    int woff = 0;
#pragma unroll
    for (int i = 0; i < 4; i++) woff += (i < w) ? wsum_s[i] : 0;
    const int incl = x + woff;
    scan_s[tid + 1] = incl;
    if (tid == 0) scan_s[0] = 0;
    __syncthreads();
    if (v) t_c[incl - 1] = t;
    if (tid < GG + 1) {
        int lo = seg_s[tid] - c0;
        lo = lo < 0 ? 0 : (lo > CHUNK ? CHUNK : lo);
        segc_s[tid] = scan_s[lo];
    }
    __syncthreads();

    if (dh == 0 && tid < GG)
        g_pcnt[(b * GG + tid) * NCHUNK + c] = (float)(segc_s[tid + 1] - segc_s[tid]);

    // ---- hot loop: sub-half of valid tokens, streaming float4 loads ----
    const int sub    = tid >> 6;          // 0 or 1
    const int lane64 = tid & 63;

    float4 acc[GG];
#pragma unroll
    for (int g = 0; g < GG; g++) acc[g] = make_float4(0.f, 0.f, 0.f, 0.f);

    const float* bb = batch + (size_t)b * TT * DD + dh * (DHF * 4) + lane64 * 4;

#pragma unroll
    for (int g = 0; g < GG; g++) {
        const int jlo = segc_s[g];
        const int jhi = segc_s[g + 1];
#pragma unroll 8
        for (int j = jlo + sub; j < jhi; j += 2) {
            const int tt2 = t_c[j];
            const float4 v4 = __ldcs((const float4*)(bb + (size_t)tt2 * DD));
            acc[g].x += v4.x; acc[g].y += v4.y; acc[g].z += v4.z; acc[g].w += v4.w;
        }
    }

    // ---- combine sub1 into sub0 deterministically, write partial ----
    if (sub == 1) {
#pragma unroll
        for (int g = 0; g < GG; g++)
            comb4[g][lane64] = acc[g];
    }
    __syncthreads();
    if (sub == 0) {
#pragma unroll
        for (int g = 0; g < GG; g++) {
            const float4 o = comb4[g][lane64];
            acc[g].x += o.x; acc[g].y += o.y; acc[g].z += o.z; acc[g].w += o.w;
            *(float4*)&g_part[(((size_t)b * GG + g) * NCHUNK + c) * DD + dh * (DHF * 4) + lane64 * 4] = acc[g];
        }
    }
}

// =====================================================================
// K2.5: reduce partials -> means [g][b][d]. Grid (B, G) = 256 blocks, 128 thr.
// =====================================================================
__global__ void __launch_bounds__(128) k_means() {
    const int b = blockIdx.x, g = blockIdx.y, tid = threadIdx.x;

    const size_t base = ((size_t)b * GG + g) * NCHUNK;
    float4 s = make_float4(0.f, 0.f, 0.f, 0.f);
    float  cnt = 0.f;
#pragma unroll 8
    for (int c = 0; c < NCHUNK; c++) {
        const float4 p = __ldcs((const float4*)&g_part[(base + c) * DD + tid * 4]);
        s.x += p.x; s.y += p.y; s.z += p.z; s.w += p.w;
        cnt += g_pcnt[base + c];
    }
    const float inv = (cnt > 0.f) ? (1.0f / cnt) : 0.0f;
    s.x *= inv; s.y *= inv; s.z *= inv; s.w *= inv;
    *(float4*)&g_means[((size_t)g * BB + b) * DD + tid * 4] = s;
}

// =====================================================================
// K3: split-K GEMM. Grid (G=8, 16 o-tiles, 16 d-tiles) = 2048 blocks, 128 thr.
// Each block: 32x32 W tile + 32x32 mean tile loaded once, 256 FFMA/thread.
// =====================================================================
__global__ void __launch_bounds__(128, 12) k_gemm3(const float* __restrict__ Wt) {
    __shared__ __align__(16) float w_s[K3D * K3B];     // 32 x 32 = 4 KB
    __shared__ __align__(16) float mean_s[BB * MP3];   // 32 x 32 (pitch 36) = 4.6 KB

    const int tid   = threadIdx.x;
    const int g     = blockIdx.x;
    const int obase = blockIdx.y * K3B;
    const int dbase = blockIdx.z * K3D;

    const float* msrc = &g_means[(size_t)g * BB * DD + dbase];
    const float* wsrc = Wt + ((size_t)g * DD + dbase) * OUTD + obase;

    // stage W tile: 256 float4, 2 per thread (coalesced)
#pragma unroll
    for (int k = 0; k < 2; k++) {
        const int i   = tid + k * 128;
        const int row = i >> 3;            // 8 float4 per 32-col row
        const int col = (i & 7) * 4;
        const float4 v = *(const float4*)(wsrc + (size_t)row * OUTD + col);
        *(float4*)&w_s[row * K3B + col] = v;
    }
    // stage mean tile: 256 float4, 2 per thread (coalesced)
#pragma unroll
    for (int k = 0; k < 2; k++) {
        const int i  = tid + k * 128;
        const int bi = i >> 3;             // 8 float4 per 32-float row
        const int du = (i & 7) * 4;
        const float4 v = *(const float4*)(msrc + (size_t)bi * DD + du);
        *(float4*)&mean_s[bi * MP3 + du] = v;
    }
    __syncthreads();

    const int olane = (tid & 7) * 4;       // 8 lanes x float4 = 32 cols
    const int brow  = (tid >> 3) * 2;      // 16 x 2 = 32 rows

    const float* m0 = &mean_s[brow * MP3];
    const float* m1 = m0 + MP3;

    float4 a0 = make_float4(0.f, 0.f, 0.f, 0.f);
    float4 a1 = make_float4(0.f, 0.f, 0.f, 0.f);

#pragma unroll
    for (int d = 0; d < K3D; d++) {
        const float4 w4 = *(const float4*)&w_s[d * K3B + olane];
        const float  x0 = m0[d];
        const float  x1 = m1[d];
        a0.x = fmaf(x0, w4.x, a0.x); a0.y = fmaf(x0, w4.y, a0.y);
        a0.z = fmaf(x0, w4.z, a0.z); a0.w = fmaf(x0, w4.w, a0.w);
        a1.x = fmaf(x1, w4.x, a1.x); a1.y = fmaf(x1, w4.y, a1.y);
        a1.w = fmaf(x1, w4.w, a1.w); a1.z = fmaf(x1, w4.z, a1.z);
    }

    const int dq = blockIdx.z;
    const int o  = obase + olane;
    *(float4*)&g_ppart[(((size_t)dq * BB + brow)     * GG + g) * OUTD + o] = a0;
    *(float4*)&g_ppart[(((size_t)dq * BB + brow + 1) * GG + g) * OUTD + o] = a1;
}

// =====================================================================
// K4: reduce split-K partials + bias -> out. Grid (B, G) = 256 blocks.
// Partials are L2-resident (8 MB). Deterministic ascending dq order.
// =====================================================================
__global__ void __launch_bounds__(128) k_out(const float* __restrict__ bias,
                                             float* __restrict__ out) {
    const int b = blockIdx.x, g = blockIdx.y, tid = threadIdx.x;
    const int o = tid * 4;

    float4 s = *(const float4*)(bias + g * OUTD + o);
#pragma unroll
    for (int dq = 0; dq < K3_ND; dq++) {
        const float4 p = __ldcs((const float4*)&g_ppart[(((size_t)dq * BB + b) * GG + g) * OUTD + o]);
        s.x += p.x; s.y += p.y; s.z += p.z; s.w += p.w;
    }
    *(float4*)(out + ((size_t)b * GG + g) * OUTD + o) = s;
}

// =====================================================================
// Launch
// =====================================================================
extern "C" void kernel_launch(void* const* d_in, const int* in_sizes, int n_in,
                              void* d_out, int out_size) {
    const float* batch = (const float*)d_in[0];
    const float* Wt    = (const float*)d_in[1];
    const float* bias  = (const float*)d_in[2];
    const int*   types = (const int*)d_in[3];
    const int*   mask  = (const int*)d_in[4];   // bool upcast to int32: nonzero = padded
    float*       out   = (float*)d_out;

    (void)in_sizes; (void)n_in; (void)out_size;

    k_sort<<<1, 512>>>(types);
    k_partial<<<dim3(BB, NCHUNK, 2), 128>>>(batch, mask);
    k_means<<<dim3(BB, GG), 128>>>();
    k_gemm3<<<dim3(GG, OUTD / K3B, K3_ND), 128>>>(Wt);
    k_out<<<dim3(BB, GG), 128>>>(bias, out);
}